// round 5
// baseline (speedup 1.0000x reference)
#include <cuda_runtime.h>

#define IN_C   128
#define OUT_C  128
#define NCLS   16
#define MAXN   100000

// ---------------- device scratch (no allocations allowed) ----------------
__device__ float g_h[(size_t)MAXN * OUT_C];      // x @ W result (51.2 MB)
__device__ float g_hcat[(size_t)MAXN * 512];     // fallback h_unmasked (204.8 MB)
__device__ float g_dis[MAXN];                    // deg, then rsqrt(deg)
__device__ int   g_is64;                         // edge_index dtype flag

// edge_index accessor: handles both int64 and int32 payloads
__device__ __forceinline__ long long edge_at(const void* p, long long i) {
    if (g_is64) return ((const long long*)p)[i];
    return (long long)((const int*)p)[i];
}

// vectorized global reduction: one RED.ADD.v4 instead of 4 scalar REDs (sm_90+)
__device__ __forceinline__ void red_add_v4(float* addr, float4 v) {
    asm volatile("red.global.add.v4.f32 [%0], {%1, %2, %3, %4};"
                 :: "l"(addr), "f"(v.x), "f"(v.y), "f"(v.z), "f"(v.w)
                 : "memory");
}

// -------- dtype detector: int32 pairs read as int64 are >= 2^32 ----------
__global__ void detect_k(const void* ei, int n) {
    __shared__ int bad;
    if (threadIdx.x == 0) bad = 0;
    __syncthreads();
    const long long* p = (const long long*)ei;
    int b = 0;
    for (int i = threadIdx.x; i < 2048; i += blockDim.x) {
        long long v = p[i];
        if (v < 0 || v >= (long long)n) b = 1;
    }
    if (b) atomicOr(&bad, 1);
    __syncthreads();
    if (threadIdx.x == 0) g_is64 = bad ? 0 : 1;
}

// ---------------- degree: deg[i] = 1 (self loop) + count(dst==i) ----------
__global__ void deg_init_k(int n) {
    int i = blockIdx.x * blockDim.x + threadIdx.x;
    if (i < n) g_dis[i] = 1.0f;
}
__global__ void deg_count_k(const void* ei, int E) {
    int e = blockIdx.x * blockDim.x + threadIdx.x;
    if (e < E) {
        long long d = edge_at(ei, (long long)E + e);
        atomicAdd(&g_dis[d], 1.0f);
    }
}
__global__ void dis_k(int n) {
    int i = blockIdx.x * blockDim.x + threadIdx.x;
    if (i < n) g_dis[i] = rsqrtf(g_dis[i]);
}

// -------- copy x into h_unmasked columns [0,128), row stride 512 ----------
__global__ void copy_x_k(const float* __restrict__ x, float* __restrict__ hcat, int n) {
    long long idx = (long long)blockIdx.x * blockDim.x + threadIdx.x;  // over n*32 float4
    if (idx >= (long long)n * 32) return;
    int i  = (int)(idx >> 5);
    int c4 = (int)(idx & 31);
    float4 v = ((const float4*)x)[(long long)i * 32 + c4];
    ((float4*)hcat)[(long long)i * 128 + c4] = v;   // 512 floats = 128 float4 per row
}

// ------ GEMM + fused self-loop/bias epilogue ------------------------------
// h[n,128]  = in[n(strided),128] @ W[128,128]           (scatter gather source)
// out[n,..] = h * dis[i]^2 + b                          (stride-512 hcat slab)
// blockDim 256, 32 nodes per block. W + staged X live in dynamic smem.
__global__ void gemm128_k(const float* __restrict__ in, int in_stride,
                          const float* __restrict__ W, const float* __restrict__ bias,
                          float* __restrict__ h, float* __restrict__ out, int n) {
    extern __shared__ float smem[];
    float* sW = smem;                 // [128][128] = 64 KB
    float* sX = smem + 128 * 128;     // [32][132]  (pad to kill bank conflicts)

    int node0 = blockIdx.x * 32;

    // load W: 4096 float4 across 256 threads
    for (int idx = threadIdx.x; idx < 4096; idx += 256) {
        ((float4*)sW)[idx] = ((const float4*)W)[idx];
    }
    // load 32 node rows (128 floats each) with row stride in_stride
    for (int idx = threadIdx.x; idx < 1024; idx += 256) {
        int row = idx >> 5, c4 = idx & 31;
        float4 v = make_float4(0.f, 0.f, 0.f, 0.f);
        if (node0 + row < n)
            v = *(const float4*)(in + (long long)(node0 + row) * in_stride + c4 * 4);
        float* d = &sX[row * 132 + c4 * 4];
        d[0] = v.x; d[1] = v.y; d[2] = v.z; d[3] = v.w;
    }
    __syncthreads();

    int node_l = threadIdx.x >> 3;          // 0..31
    int cb     = (threadIdx.x & 7) * 16;    // 16 output channels per thread
    float acc[16];
#pragma unroll
    for (int j = 0; j < 16; j++) acc[j] = 0.f;

#pragma unroll 8
    for (int k = 0; k < 128; k++) {
        float xv = sX[node_l * 132 + k];
        const float4* wr = (const float4*)&sW[k * 128 + cb];
        float4 w0 = wr[0], w1 = wr[1], w2 = wr[2], w3 = wr[3];
        acc[0]  += xv * w0.x; acc[1]  += xv * w0.y; acc[2]  += xv * w0.z; acc[3]  += xv * w0.w;
        acc[4]  += xv * w1.x; acc[5]  += xv * w1.y; acc[6]  += xv * w1.z; acc[7]  += xv * w1.w;
        acc[8]  += xv * w2.x; acc[9]  += xv * w2.y; acc[10] += xv * w2.z; acc[11] += xv * w2.w;
        acc[12] += xv * w3.x; acc[13] += xv * w3.y; acc[14] += xv * w3.z; acc[15] += xv * w3.w;
    }

    int node = node0 + node_l;
    if (node < n) {
        float4* o = (float4*)(h + (long long)node * 128 + cb);
        o[0] = make_float4(acc[0],  acc[1],  acc[2],  acc[3]);
        o[1] = make_float4(acc[4],  acc[5],  acc[6],  acc[7]);
        o[2] = make_float4(acc[8],  acc[9],  acc[10], acc[11]);
        o[3] = make_float4(acc[12], acc[13], acc[14], acc[15]);

        // fused self-loop + bias init of the aggregation output
        float di = g_dis[node];
        float d2 = di * di;
        const float4* bv4 = (const float4*)(bias + cb);
        float4 b0 = bv4[0], b1 = bv4[1], b2 = bv4[2], b3 = bv4[3];
        float4* oc = (float4*)(out + (long long)node * 512 + cb);
        oc[0] = make_float4(acc[0]*d2 + b0.x,  acc[1]*d2 + b0.y,  acc[2]*d2 + b0.z,  acc[3]*d2 + b0.w);
        oc[1] = make_float4(acc[4]*d2 + b1.x,  acc[5]*d2 + b1.y,  acc[6]*d2 + b1.z,  acc[7]*d2 + b1.w);
        oc[2] = make_float4(acc[8]*d2 + b2.x,  acc[9]*d2 + b2.y,  acc[10]*d2 + b2.z, acc[11]*d2 + b2.w);
        oc[3] = make_float4(acc[12]*d2 + b3.x, acc[13]*d2 + b3.y, acc[14]*d2 + b3.z, acc[15]*d2 + b3.w);
    }
}

// ---- scatter: one warp per edge; out[dst] += h[src] * dis[src]*dis[dst] --
// lane 0 loads edge indices + norm once, broadcasts via shfl (kills 62
// redundant index LDGs per edge).
__global__ void scatter_k(const void* __restrict__ ei, const float* __restrict__ h,
                          float* __restrict__ out, int E) {
    int w    = (int)(((long long)blockIdx.x * blockDim.x + threadIdx.x) >> 5);
    int lane = threadIdx.x & 31;
    if (w >= E) return;
    long long s = 0, d = 0;
    float nw = 0.f;
    if (lane == 0) {
        s  = edge_at(ei, w);
        d  = edge_at(ei, (long long)E + w);
        nw = g_dis[s] * g_dis[d];
    }
    s  = __shfl_sync(0xffffffffu, s, 0);
    d  = __shfl_sync(0xffffffffu, d, 0);
    nw = __shfl_sync(0xffffffffu, nw, 0);
    float4 v = ((const float4*)(h + s * 128))[lane];
    float* o = out + d * 512 + lane * 4;
    red_add_v4(o, make_float4(v.x * nw, v.y * nw, v.z * nw, v.w * nw));
}

// ---------------- final head: labels = hcat[n,512] @ W_lin[512,16] + b ----
__global__ void final_k(const float* __restrict__ hcat, const float* __restrict__ Wl,
                        const float* __restrict__ bl, float* __restrict__ out, int n) {
    __shared__ float sW[512 * 16];   // 32 KB
    __shared__ float sB[16];
    for (int idx = threadIdx.x; idx < 512 * 16 / 4; idx += blockDim.x)
        ((float4*)sW)[idx] = ((const float4*)Wl)[idx];
    if (threadIdx.x < 16) sB[threadIdx.x] = bl[threadIdx.x];
    __syncthreads();

    int i = blockIdx.x * blockDim.x + threadIdx.x;
    if (i >= n) return;

    float4 acc[4];
#pragma unroll
    for (int j = 0; j < 4; j++)
        acc[j] = make_float4(sB[j * 4], sB[j * 4 + 1], sB[j * 4 + 2], sB[j * 4 + 3]);

    const float4* row = (const float4*)(hcat + (long long)i * 512);
#pragma unroll 4
    for (int k4 = 0; k4 < 128; k4++) {
        float4 r = row[k4];
        float rv[4] = {r.x, r.y, r.z, r.w};
#pragma unroll
        for (int kk = 0; kk < 4; kk++) {
            int k = k4 * 4 + kk;
            const float4* wr = (const float4*)&sW[k * 16];
#pragma unroll
            for (int j = 0; j < 4; j++) {
                float4 wv = wr[j];
                acc[j].x += rv[kk] * wv.x;
                acc[j].y += rv[kk] * wv.y;
                acc[j].z += rv[kk] * wv.z;
                acc[j].w += rv[kk] * wv.w;
            }
        }
    }
    float4* o = (float4*)(out + (long long)i * 16);
#pragma unroll
    for (int j = 0; j < 4; j++) o[j] = acc[j];
}

// --------------------------------------------------------------------------
extern "C" void kernel_launch(void* const* d_in, const int* in_sizes, int n_in,
                              void* d_out, int out_size) {
    const float* x   = (const float*)d_in[0];
    const void*  ei  = d_in[1];
    const float* W1  = (const float*)d_in[2];
    const float* b1  = (const float*)d_in[3];
    const float* W2  = (const float*)d_in[4];
    const float* b2  = (const float*)d_in[5];
    const float* W3  = (const float*)d_in[6];
    const float* b3  = (const float*)d_in[7];
    const float* Wl  = (const float*)d_in[8];
    const float* bl  = (const float*)d_in[9];

    int n = in_sizes[0] / IN_C;
    int E = in_sizes[1] / 2;

    float* out = (float*)d_out;

    // h_unmasked location: inside d_out if it holds [labels | hcat], else scratch
    float* hcat;
    if ((long long)out_size >= (long long)n * (NCLS + 512)) {
        hcat = out + (long long)n * NCLS;
    } else {
        cudaGetSymbolAddress((void**)&hcat, g_hcat);
    }

    float* d_h;
    cudaGetSymbolAddress((void**)&d_h, g_h);

    const int T = 256;
    int gemm_smem = 128 * 128 * 4 + 32 * 132 * 4;
    cudaFuncSetAttribute(gemm128_k, cudaFuncAttributeMaxDynamicSharedMemorySize, gemm_smem);

    // dtype detection + normalization coefficients
    detect_k<<<1, 256>>>(ei, n);
    deg_init_k<<<(n + T - 1) / T, T>>>(n);
    deg_count_k<<<(E + T - 1) / T, T>>>(ei, E);
    dis_k<<<(n + T - 1) / T, T>>>(n);

    // xs[0] = x into hcat columns [0,128)
    long long v4 = (long long)n * 32;
    copy_x_k<<<(unsigned)((v4 + T - 1) / T), T>>>(x, hcat, n);

    const float* Ws[3] = {W1, W2, W3};
    const float* bs[3] = {b1, b2, b3};
    for (int l = 0; l < 3; l++) {
        const float* in_ptr  = (l == 0) ? x : (hcat + l * 128);
        int          in_str  = (l == 0) ? 128 : 512;
        float*       out_ptr = hcat + (l + 1) * 128;

        gemm128_k<<<(n + 31) / 32, T, gemm_smem>>>(in_ptr, in_str, Ws[l], bs[l],
                                                   d_h, out_ptr, n);
        long long sth = (long long)E * 32;
        scatter_k<<<(unsigned)((sth + T - 1) / T), T>>>(ei, d_h, out_ptr, E);
    }

    final_k<<<(n + T - 1) / T, T>>>(hcat, Wl, bl, out, n);
}

// round 8
// speedup vs baseline: 1.1755x; 1.1755x over previous
#include <cuda_runtime.h>

#define IN_C   128
#define OUT_C  128
#define NCLS   16
#define MAXN   100000
#define MAXE   1700000

// ---------------- device scratch (no allocations allowed) ----------------
__device__ float g_h[(size_t)MAXN * OUT_C];      // x @ W result (51.2 MB)
__device__ float g_hcat[(size_t)MAXN * 512];     // fallback h_unmasked (204.8 MB)
__device__ float g_dis[MAXN];                    // rsqrt(deg)
__device__ int   g_deg[MAXN];                    // in-degree (edges only)
__device__ int   g_rowptr[MAXN];                 // CSR row starts
__device__ int   g_cursor[MAXN];                 // CSR fill cursors
__device__ int   g_bsum[128];                    // scan spine
__device__ int2  g_edges[MAXE];                  // CSR payload: (src, bitcast norm)
__device__ int   g_is64;                         // edge_index dtype flag

// edge_index accessor: handles both int64 and int32 payloads
__device__ __forceinline__ long long edge_at(const void* p, long long i) {
    if (g_is64) return ((const long long*)p)[i];
    return (long long)((const int*)p)[i];
}

// -------- dtype detector: int32 pairs read as int64 are >= 2^32 ----------
__global__ void detect_k(const void* ei, int n) {
    __shared__ int bad;
    if (threadIdx.x == 0) bad = 0;
    __syncthreads();
    const long long* p = (const long long*)ei;
    int b = 0;
    for (int i = threadIdx.x; i < 2048; i += blockDim.x) {
        long long v = p[i];
        if (v < 0 || v >= (long long)n) b = 1;
    }
    if (b) atomicOr(&bad, 1);
    __syncthreads();
    if (threadIdx.x == 0) g_is64 = bad ? 0 : 1;
}

// ---------------- degree / CSR construction ------------------------------
__global__ void zero_k(int n) {
    int i = blockIdx.x * blockDim.x + threadIdx.x;
    if (i < n) g_deg[i] = 0;
}
__global__ void deg_count_k(const void* ei, int E) {
    int e = blockIdx.x * blockDim.x + threadIdx.x;
    if (e < E) {
        int d = (int)edge_at(ei, (long long)E + e);
        atomicAdd(&g_deg[d], 1);
    }
}
__global__ void dis_k(int n) {
    int i = blockIdx.x * blockDim.x + threadIdx.x;
    if (i < n) g_dis[i] = rsqrtf((float)(g_deg[i] + 1));   // +1 self loop
}
// exclusive scan, 1024 elems/block
__global__ void scan1_k(int n) {
    __shared__ int s[1024];
    int t = threadIdx.x;
    int i = blockIdx.x * 1024 + t;
    int v = (i < n) ? g_deg[i] : 0;
    s[t] = v;
    __syncthreads();
    for (int off = 1; off < 1024; off <<= 1) {
        int add = (t >= off) ? s[t - off] : 0;
        __syncthreads();
        s[t] += add;
        __syncthreads();
    }
    if (i < n) g_rowptr[i] = s[t] - v;        // exclusive
    if (t == 1023) g_bsum[blockIdx.x] = s[1023];
}
__global__ void scan2_k(int nb) {
    if (threadIdx.x == 0) {
        int acc = 0;
        for (int i = 0; i < nb; i++) { int v = g_bsum[i]; g_bsum[i] = acc; acc += v; }
    }
}
__global__ void scan3_k(int n) {
    int i = blockIdx.x * 1024 + threadIdx.x;
    if (i < n) {
        g_rowptr[i] += g_bsum[blockIdx.x];
        g_cursor[i] = 0;
    }
}
__global__ void fill_k(const void* __restrict__ ei, int E) {
    int e = blockIdx.x * blockDim.x + threadIdx.x;
    if (e >= E) return;
    int s = (int)edge_at(ei, e);
    int d = (int)edge_at(ei, (long long)E + e);
    float nw = g_dis[s] * g_dis[d];
    int slot = g_rowptr[d] + atomicAdd(&g_cursor[d], 1);
    if (slot < MAXE) g_edges[slot] = make_int2(s, __float_as_int(nw));
}

// -------- copy x into h_unmasked columns [0,128), row stride 512 ----------
__global__ void copy_x_k(const float* __restrict__ x, float* __restrict__ hcat, int n) {
    long long idx = (long long)blockIdx.x * blockDim.x + threadIdx.x;
    if (idx >= (long long)n * 32) return;
    int i  = (int)(idx >> 5);
    int c4 = (int)(idx & 31);
    float4 v = ((const float4*)x)[(long long)i * 32 + c4];
    ((float4*)hcat)[(long long)i * 128 + c4] = v;
}

// ---------------- GEMM: h[n,128] = in[n(strided),128] @ W[128,128] --------
__global__ void gemm128_k(const float* __restrict__ in, int in_stride,
                          const float* __restrict__ W,
                          float* __restrict__ h, int n) {
    extern __shared__ float smem[];
    float* sW = smem;                 // [128][128] = 64 KB
    float* sX = smem + 128 * 128;     // [32][132]

    int node0 = blockIdx.x * 32;

    for (int idx = threadIdx.x; idx < 4096; idx += 256)
        ((float4*)sW)[idx] = ((const float4*)W)[idx];
    for (int idx = threadIdx.x; idx < 1024; idx += 256) {
        int row = idx >> 5, c4 = idx & 31;
        float4 v = make_float4(0.f, 0.f, 0.f, 0.f);
        if (node0 + row < n)
            v = *(const float4*)(in + (long long)(node0 + row) * in_stride + c4 * 4);
        float* d = &sX[row * 132 + c4 * 4];
        d[0] = v.x; d[1] = v.y; d[2] = v.z; d[3] = v.w;
    }
    __syncthreads();

    int node_l = threadIdx.x >> 3;
    int cb     = (threadIdx.x & 7) * 16;
    float acc[16];
#pragma unroll
    for (int j = 0; j < 16; j++) acc[j] = 0.f;

#pragma unroll 8
    for (int k = 0; k < 128; k++) {
        float xv = sX[node_l * 132 + k];
        const float4* wr = (const float4*)&sW[k * 128 + cb];
        float4 w0 = wr[0], w1 = wr[1], w2 = wr[2], w3 = wr[3];
        acc[0]  += xv * w0.x; acc[1]  += xv * w0.y; acc[2]  += xv * w0.z; acc[3]  += xv * w0.w;
        acc[4]  += xv * w1.x; acc[5]  += xv * w1.y; acc[6]  += xv * w1.z; acc[7]  += xv * w1.w;
        acc[8]  += xv * w2.x; acc[9]  += xv * w2.y; acc[10] += xv * w2.z; acc[11] += xv * w2.w;
        acc[12] += xv * w3.x; acc[13] += xv * w3.y; acc[14] += xv * w3.z; acc[15] += xv * w3.w;
    }

    int node = node0 + node_l;
    if (node < n) {
        float4* o = (float4*)(h + (long long)node * 128 + cb);
        o[0] = make_float4(acc[0],  acc[1],  acc[2],  acc[3]);
        o[1] = make_float4(acc[4],  acc[5],  acc[6],  acc[7]);
        o[2] = make_float4(acc[8],  acc[9],  acc[10], acc[11]);
        o[3] = make_float4(acc[12], acc[13], acc[14], acc[15]);
    }
}

// ---- aggregation: warp per dst node, NO atomics --------------------------
// out[d] = h[d]*dis[d]^2 + b + sum_{e in CSR row d} h[src_e]*nw_e
__global__ void agg_k(const float* __restrict__ h, const float* __restrict__ bias,
                      float* __restrict__ out, int n) {
    int warp = (int)(((long long)blockIdx.x * blockDim.x + threadIdx.x) >> 5);
    int lane = threadIdx.x & 31;
    if (warp >= n) return;

    int node = warp;
    // issue CSR metadata loads first so the edge stream starts early
    int beg = g_rowptr[node];
    int cnt = g_deg[node];

    float di = g_dis[node];
    float d2 = di * di;

    float4 hv = __ldg(((const float4*)(h + (long long)node * 128)) + lane);
    float4 bv = __ldg(((const float4*)bias) + lane);
    float4 acc = make_float4(hv.x * d2 + bv.x, hv.y * d2 + bv.y,
                             hv.z * d2 + bv.z, hv.w * d2 + bv.w);

    for (int base = 0; base < cnt; base += 32) {
        int e = base + lane;
        int src = 0; float nw = 0.f;
        if (e < cnt) {
            int2 p = __ldg(&g_edges[beg + e]);
            src = p.x;
            nw  = __int_as_float(p.y);
        }
        int m = min(32, cnt - base);
        for (int j = 0; j < m; j++) {
            int   s = __shfl_sync(0xffffffffu, src, j);
            float w = __shfl_sync(0xffffffffu, nw,  j);
            float4 v = __ldg(((const float4*)(h + (long long)s * 128)) + lane);
            acc.x += v.x * w; acc.y += v.y * w; acc.z += v.z * w; acc.w += v.w * w;
        }
    }
    ((float4*)(out + (long long)node * 512))[lane] = acc;
}

// ---------------- final head: labels = hcat[n,512] @ W_lin[512,16] + b ----
__global__ void final_k(const float* __restrict__ hcat, const float* __restrict__ Wl,
                        const float* __restrict__ bl, float* __restrict__ out, int n) {
    __shared__ float sW[512 * 16];
    __shared__ float sB[16];
    for (int idx = threadIdx.x; idx < 512 * 16 / 4; idx += blockDim.x)
        ((float4*)sW)[idx] = ((const float4*)Wl)[idx];
    if (threadIdx.x < 16) sB[threadIdx.x] = bl[threadIdx.x];
    __syncthreads();

    int i = blockIdx.x * blockDim.x + threadIdx.x;
    if (i >= n) return;

    float4 acc[4];
#pragma unroll
    for (int j = 0; j < 4; j++)
        acc[j] = make_float4(sB[j * 4], sB[j * 4 + 1], sB[j * 4 + 2], sB[j * 4 + 3]);

    const float4* row = (const float4*)(hcat + (long long)i * 512);
#pragma unroll 4
    for (int k4 = 0; k4 < 128; k4++) {
        float4 r = row[k4];
        float rv[4] = {r.x, r.y, r.z, r.w};
#pragma unroll
        for (int kk = 0; kk < 4; kk++) {
            int k = k4 * 4 + kk;
            const float4* wr = (const float4*)&sW[k * 16];
#pragma unroll
            for (int j = 0; j < 4; j++) {
                float4 wv = wr[j];
                acc[j].x += rv[kk] * wv.x;
                acc[j].y += rv[kk] * wv.y;
                acc[j].z += rv[kk] * wv.z;
                acc[j].w += rv[kk] * wv.w;
            }
        }
    }
    float4* o = (float4*)(out + (long long)i * 16);
#pragma unroll
    for (int j = 0; j < 4; j++) o[j] = acc[j];
}

// --------------------------------------------------------------------------
extern "C" void kernel_launch(void* const* d_in, const int* in_sizes, int n_in,
                              void* d_out, int out_size) {
    const float* x   = (const float*)d_in[0];
    const void*  ei  = d_in[1];
    const float* W1  = (const float*)d_in[2];
    const float* b1  = (const float*)d_in[3];
    const float* W2  = (const float*)d_in[4];
    const float* b2  = (const float*)d_in[5];
    const float* W3  = (const float*)d_in[6];
    const float* b3  = (const float*)d_in[7];
    const float* Wl  = (const float*)d_in[8];
    const float* bl  = (const float*)d_in[9];

    int n = in_sizes[0] / IN_C;
    int E = in_sizes[1] / 2;

    float* out = (float*)d_out;

    float* hcat;
    if ((long long)out_size >= (long long)n * (NCLS + 512)) {
        hcat = out + (long long)n * NCLS;
    } else {
        cudaGetSymbolAddress((void**)&hcat, g_hcat);
    }

    float* d_h;
    cudaGetSymbolAddress((void**)&d_h, g_h);

    const int T = 256;
    int gemm_smem = 128 * 128 * 4 + 32 * 132 * 4;
    cudaFuncSetAttribute(gemm128_k, cudaFuncAttributeMaxDynamicSharedMemorySize, gemm_smem);

    int nb1024 = (n + 1023) / 1024;

    // ---- CSR build ----
    detect_k<<<1, 256>>>(ei, n);
    zero_k<<<(n + T - 1) / T, T>>>(n);
    deg_count_k<<<(E + T - 1) / T, T>>>(ei, E);
    dis_k<<<(n + T - 1) / T, T>>>(n);
    scan1_k<<<nb1024, 1024>>>(n);
    scan2_k<<<1, 32>>>(nb1024);
    scan3_k<<<nb1024, 1024>>>(n);
    fill_k<<<(E + T - 1) / T, T>>>(ei, E);

    // ---- xs[0] = x ----
    long long v4 = (long long)n * 32;
    copy_x_k<<<(unsigned)((v4 + T - 1) / T), T>>>(x, hcat, n);

    // ---- 3 GCN layers: GEMM then gather-aggregate (no atomics) ----
    const float* Ws[3] = {W1, W2, W3};
    const float* bs[3] = {b1, b2, b3};
    for (int l = 0; l < 3; l++) {
        const float* in_ptr  = (l == 0) ? x : (hcat + l * 128);
        int          in_str  = (l == 0) ? 128 : 512;
        float*       out_ptr = hcat + (l + 1) * 128;

        gemm128_k<<<(n + 31) / 32, T, gemm_smem>>>(in_ptr, in_str, Ws[l], d_h, n);
        int AT = 512;                                     // 16 warps/block
        int agg_blocks = (n * 32 + AT - 1) / AT;
        agg_k<<<agg_blocks, AT>>>(d_h, bs[l], out_ptr, n);
    }

    final_k<<<(n + T - 1) / T, T>>>(hcat, Wl, bl, out, n);
}

// round 9
// speedup vs baseline: 3.9542x; 3.3639x over previous
#include <cuda_runtime.h>

#define IN_C   128
#define OUT_C  128
#define NCLS   16
#define MAXN   100000
#define MAXE   1700000

// ---------------- device scratch (no allocations allowed) ----------------
__device__ float g_h[(size_t)MAXN * OUT_C];      // x @ W result (51.2 MB)
__device__ float g_hcat[(size_t)MAXN * 512];     // fallback h_unmasked
__device__ float g_dis[MAXN];                    // rsqrt(deg)
__device__ int   g_deg[MAXN];                    // in-degree (edges only)
__device__ int   g_rowptr[MAXN];                 // CSR row starts
__device__ int   g_cursor[MAXN];                 // CSR fill cursors
__device__ int   g_bsum[128];                    // scan spine
__device__ int2  g_edges[MAXE];                  // CSR payload: (src, bitcast norm)
__device__ int   g_is64;                         // edge_index dtype flag

__device__ __forceinline__ long long edge_at(const void* p, long long i) {
    if (g_is64) return ((const long long*)p)[i];
    return (long long)((const int*)p)[i];
}

// ---- launch 0: fused dtype detect + deg zero -----------------------------
__global__ void init_k(const void* ei, int n) {
    int i = blockIdx.x * blockDim.x + threadIdx.x;
    if (i < n) g_deg[i] = 0;
    if (blockIdx.x == 0) {
        __shared__ int bad;
        if (threadIdx.x == 0) bad = 0;
        __syncthreads();
        const long long* p = (const long long*)ei;
        int b = 0;
        for (int j = threadIdx.x; j < 2048; j += blockDim.x) {
            long long v = p[j];
            if (v < 0 || v >= (long long)n) b = 1;
        }
        if (b) atomicOr(&bad, 1);
        __syncthreads();
        if (threadIdx.x == 0) g_is64 = bad ? 0 : 1;
    }
}

// ---- launch 1: in-degree count -------------------------------------------
__global__ void deg_count_k(const void* ei, int E) {
    int e = blockIdx.x * blockDim.x + threadIdx.x;
    if (e < E) {
        int d = (int)edge_at(ei, (long long)E + e);
        atomicAdd(&g_deg[d], 1);
    }
}

// ---- launch 2: block-local exclusive scan + dis --------------------------
__global__ void scan1_k(int n) {
    __shared__ int s[1024];
    int t = threadIdx.x;
    int i = blockIdx.x * 1024 + t;
    int v = (i < n) ? g_deg[i] : 0;
    s[t] = v;
    __syncthreads();
    for (int off = 1; off < 1024; off <<= 1) {
        int add = (t >= off) ? s[t - off] : 0;
        __syncthreads();
        s[t] += add;
        __syncthreads();
    }
    if (i < n) {
        g_rowptr[i] = s[t] - v;                  // exclusive within block
        g_dis[i]    = rsqrtf((float)(v + 1));    // +1 self loop
    }
    if (t == 1023) g_bsum[blockIdx.x] = s[1023];
}

// ---- launch 4: cross-block offset (inline spine) + cursor reset ----------
__global__ void scan3_k(int n, int nb) {
    __shared__ int sb[128];
    __shared__ int base;
    int t = threadIdx.x;
    if (t < nb) sb[t] = g_bsum[t];
    __syncthreads();
    if (t == 0) {
        int a = 0;
        for (int j = 0; j < blockIdx.x; j++) a += sb[j];
        base = a;
    }
    __syncthreads();
    int i = blockIdx.x * 1024 + t;
    if (i < n) {
        g_rowptr[i] += base;
        g_cursor[i] = 0;
    }
}

// ---- launch 5: CSR fill ---------------------------------------------------
__global__ void fill_k(const void* __restrict__ ei, int E) {
    int e = blockIdx.x * blockDim.x + threadIdx.x;
    if (e >= E) return;
    int s = (int)edge_at(ei, e);
    int d = (int)edge_at(ei, (long long)E + e);
    float nw = g_dis[s] * g_dis[d];
    int slot = g_rowptr[d] + atomicAdd(&g_cursor[d], 1);
    if (slot < MAXE) g_edges[slot] = make_int2(s, __float_as_int(nw));
}

// ---- copy x into hcat columns [0,128), row stride 512 --------------------
__global__ void copy_x_k(const float* __restrict__ x, float* __restrict__ hcat, int n) {
    long long idx = (long long)blockIdx.x * blockDim.x + threadIdx.x;
    if (idx >= (long long)n * 32) return;
    int i  = (int)(idx >> 5);
    int c4 = (int)(idx & 31);
    float4 v = ((const float4*)x)[(long long)i * 32 + c4];
    ((float4*)hcat)[(long long)i * 128 + c4] = v;
}

// ---- GEMM: h[n,128] = in[n(strided),128] @ W[128,128] --------------------
// 64 nodes/block, 256 threads, thread tile = 8 nodes x 4 channels.
// Per warp per k: 1 contiguous LDS.128 of W + 8 broadcast x LDS + 32 FFMA.
__global__ void gemm128_k(const float* __restrict__ in, int in_stride,
                          const float* __restrict__ W,
                          float* __restrict__ h, int n) {
    extern __shared__ float smem[];
    float* sW = smem;                 // [128][128] = 64 KB
    float* sX = smem + 128 * 128;     // [64][132]  = 33.8 KB

    int node0 = blockIdx.x * 64;

    for (int idx = threadIdx.x; idx < 4096; idx += 256)
        ((float4*)sW)[idx] = ((const float4*)W)[idx];
    for (int idx = threadIdx.x; idx < 2048; idx += 256) {
        int row = idx >> 5, c4 = idx & 31;
        float4 v = make_float4(0.f, 0.f, 0.f, 0.f);
        if (node0 + row < n)
            v = *(const float4*)(in + (long long)(node0 + row) * in_stride + c4 * 4);
        float* d = &sX[row * 132 + c4 * 4];
        d[0] = v.x; d[1] = v.y; d[2] = v.z; d[3] = v.w;
    }
    __syncthreads();

    int ch4  = threadIdx.x & 31;     // channel group: channels ch4*4 .. +3
    int ngrp = threadIdx.x >> 5;     // node group: nodes ngrp*8 .. +7

    float4 acc[8];
#pragma unroll
    for (int i = 0; i < 8; i++) acc[i] = make_float4(0.f, 0.f, 0.f, 0.f);

    const float* xb = &sX[ngrp * 8 * 132];

#pragma unroll 4
    for (int k = 0; k < 128; k++) {
        float4 wv = *(const float4*)&sW[k * 128 + ch4 * 4];
#pragma unroll
        for (int i = 0; i < 8; i++) {
            float xv = xb[i * 132 + k];
            acc[i].x += xv * wv.x;
            acc[i].y += xv * wv.y;
            acc[i].z += xv * wv.z;
            acc[i].w += xv * wv.w;
        }
    }

#pragma unroll
    for (int i = 0; i < 8; i++) {
        int node = node0 + ngrp * 8 + i;
        if (node < n)
            *(float4*)(h + (long long)node * 128 + ch4 * 4) = acc[i];
    }
}

// ---- aggregation: warp per dst node, no atomics, high-MLP unrolled -------
// out[d] = h[d]*dis[d]^2 + b + sum_{e in row d} h[src_e]*nw_e
__global__ void agg_k(const float* __restrict__ h, const float* __restrict__ bias,
                      float* __restrict__ out, int n) {
    int warp = (int)(((long long)blockIdx.x * blockDim.x + threadIdx.x) >> 5);
    int lane = threadIdx.x & 31;
    if (warp >= n) return;

    int node = warp;
    int beg = g_rowptr[node];
    int cnt = g_deg[node];

    float di = g_dis[node];
    float d2 = di * di;

    float4 hv = __ldg(((const float4*)(h + (long long)node * 128)) + lane);
    float4 bv = __ldg(((const float4*)bias) + lane);
    float4 acc = make_float4(hv.x * d2 + bv.x, hv.y * d2 + bv.y,
                             hv.z * d2 + bv.z, hv.w * d2 + bv.w);

    for (int base = 0; base < cnt; base += 32) {
        int e = base + lane;
        int2 p = make_int2(0, 0);                 // src=0 (L1-hot), w=0
        if (e < cnt) p = __ldg(&g_edges[beg + e]);
        int src = p.x;
        float nw = __int_as_float(p.y);
        // full static unroll -> ptxas front-batches the 32 independent LDG.128
#pragma unroll
        for (int j = 0; j < 32; j++) {
            int   s = __shfl_sync(0xffffffffu, src, j);
            float w = __shfl_sync(0xffffffffu, nw,  j);
            float4 v = __ldg(((const float4*)(h + (long long)s * 128)) + lane);
            acc.x += v.x * w; acc.y += v.y * w; acc.z += v.z * w; acc.w += v.w * w;
        }
    }
    ((float4*)(out + (long long)node * 512))[lane] = acc;
}

// ---- final head: labels = hcat[n,512] @ W_lin[512,16] + b ----------------
__global__ void final_k(const float* __restrict__ hcat, const float* __restrict__ Wl,
                        const float* __restrict__ bl, float* __restrict__ out, int n) {
    __shared__ float sW[512 * 16];
    __shared__ float sB[16];
    for (int idx = threadIdx.x; idx < 512 * 16 / 4; idx += blockDim.x)
        ((float4*)sW)[idx] = ((const float4*)Wl)[idx];
    if (threadIdx.x < 16) sB[threadIdx.x] = bl[threadIdx.x];
    __syncthreads();

    int i = blockIdx.x * blockDim.x + threadIdx.x;
    if (i >= n) return;

    float4 acc[4];
#pragma unroll
    for (int j = 0; j < 4; j++)
        acc[j] = make_float4(sB[j * 4], sB[j * 4 + 1], sB[j * 4 + 2], sB[j * 4 + 3]);

    const float4* row = (const float4*)(hcat + (long long)i * 512);
#pragma unroll 4
    for (int k4 = 0; k4 < 128; k4++) {
        float4 r = row[k4];
        float rv[4] = {r.x, r.y, r.z, r.w};
#pragma unroll
        for (int kk = 0; kk < 4; kk++) {
            int k = k4 * 4 + kk;
            const float4* wr = (const float4*)&sW[k * 16];
#pragma unroll
            for (int j = 0; j < 4; j++) {
                float4 wv = wr[j];
                acc[j].x += rv[kk] * wv.x;
                acc[j].y += rv[kk] * wv.y;
                acc[j].z += rv[kk] * wv.z;
                acc[j].w += rv[kk] * wv.w;
            }
        }
    }
    float4* o = (float4*)(out + (long long)i * 16);
#pragma unroll
    for (int j = 0; j < 4; j++) o[j] = acc[j];
}

// --------------------------------------------------------------------------
extern "C" void kernel_launch(void* const* d_in, const int* in_sizes, int n_in,
                              void* d_out, int out_size) {
    const float* x   = (const float*)d_in[0];
    const void*  ei  = d_in[1];
    const float* W1  = (const float*)d_in[2];
    const float* b1  = (const float*)d_in[3];
    const float* W2  = (const float*)d_in[4];
    const float* b2  = (const float*)d_in[5];
    const float* W3  = (const float*)d_in[6];
    const float* b3  = (const float*)d_in[7];
    const float* Wl  = (const float*)d_in[8];
    const float* bl  = (const float*)d_in[9];

    int n = in_sizes[0] / IN_C;
    int E = in_sizes[1] / 2;

    float* out = (float*)d_out;

    float* hcat;
    if ((long long)out_size >= (long long)n * (NCLS + 512)) {
        hcat = out + (long long)n * NCLS;
    } else {
        cudaGetSymbolAddress((void**)&hcat, g_hcat);
    }

    float* d_h;
    cudaGetSymbolAddress((void**)&d_h, g_h);

    const int T = 256;
    int gemm_smem = 128 * 128 * 4 + 64 * 132 * 4;   // 99.3 KB
    cudaFuncSetAttribute(gemm128_k, cudaFuncAttributeMaxDynamicSharedMemorySize, gemm_smem);

    int nb1024 = (n + 1023) / 1024;
    long long v4 = (long long)n * 32;

    // launch order chosen so gemm1 lands at profiled slot (index 3)
    init_k<<<(n + T - 1) / T, T>>>(ei, n);                              // 0
    deg_count_k<<<(E + T - 1) / T, T>>>(ei, E);                         // 1
    scan1_k<<<nb1024, 1024>>>(n);                                       // 2
    gemm128_k<<<(n + 63) / 64, T, gemm_smem>>>(x, 128, W1, d_h, n);     // 3 <- ncu
    scan3_k<<<nb1024, 1024>>>(n, nb1024);                               // 4
    fill_k<<<(E + T - 1) / T, T>>>(ei, E);                              // 5
    copy_x_k<<<(unsigned)((v4 + T - 1) / T), T>>>(x, hcat, n);          // 6

    const float* Ws[3] = {W1, W2, W3};
    const float* bs[3] = {b1, b2, b3};
    for (int l = 0; l < 3; l++) {
        float* out_ptr = hcat + (l + 1) * 128;
        if (l > 0) {
            gemm128_k<<<(n + 63) / 64, T, gemm_smem>>>(hcat + l * 128, 512, Ws[l], d_h, n);
        }
        int AT = 512;
        int agg_blocks = (n * 32 + AT - 1) / AT;
        agg_k<<<agg_blocks, AT>>>(d_h, bs[l], out_ptr, n);
    }

    final_k<<<(n + T - 1) / T, T>>>(hcat, Wl, bl, out, n);
}

// round 10
// speedup vs baseline: 4.0846x; 1.0330x over previous
#include <cuda_runtime.h>

#define IN_C   128
#define OUT_C  128
#define NCLS   16
#define MAXN   100000
#define MAXE   1700000

// ---------------- device scratch (no allocations allowed) ----------------
__device__ float g_h[(size_t)MAXN * OUT_C];      // x @ W result (51.2 MB)
__device__ float g_hcat[(size_t)MAXN * 512];     // fallback h_unmasked
__device__ float g_dis[MAXN];                    // rsqrt(deg)
__device__ int   g_deg[MAXN];                    // in-degree (edges only)
__device__ int   g_rowptr[MAXN];                 // CSR row starts
__device__ int   g_cursor[MAXN];                 // CSR fill cursors
__device__ int   g_bsum[128];                    // scan spine
__device__ int2  g_edges[MAXE];                  // CSR payload: (src, bitcast norm)
__device__ int   g_is64;                         // edge_index dtype flag

__device__ __forceinline__ long long edge_at(const void* p, long long i) {
    if (g_is64) return ((const long long*)p)[i];
    return (long long)((const int*)p)[i];
}

// ---- launch 0: fused dtype detect + deg zero -----------------------------
__global__ void init_k(const void* ei, int n) {
    int i = blockIdx.x * blockDim.x + threadIdx.x;
    if (i < n) g_deg[i] = 0;
    if (blockIdx.x == 0) {
        __shared__ int bad;
        if (threadIdx.x == 0) bad = 0;
        __syncthreads();
        const long long* p = (const long long*)ei;
        int b = 0;
        for (int j = threadIdx.x; j < 2048; j += blockDim.x) {
            long long v = p[j];
            if (v < 0 || v >= (long long)n) b = 1;
        }
        if (b) atomicOr(&bad, 1);
        __syncthreads();
        if (threadIdx.x == 0) g_is64 = bad ? 0 : 1;
    }
}

// ---- launch 1: in-degree count -------------------------------------------
__global__ void deg_count_k(const void* ei, int E) {
    int e = blockIdx.x * blockDim.x + threadIdx.x;
    if (e < E) {
        int d = (int)edge_at(ei, (long long)E + e);
        atomicAdd(&g_deg[d], 1);
    }
}

// ---- launch 2: block-local exclusive scan + dis --------------------------
__global__ void scan1_k(int n) {
    __shared__ int s[1024];
    int t = threadIdx.x;
    int i = blockIdx.x * 1024 + t;
    int v = (i < n) ? g_deg[i] : 0;
    s[t] = v;
    __syncthreads();
    for (int off = 1; off < 1024; off <<= 1) {
        int add = (t >= off) ? s[t - off] : 0;
        __syncthreads();
        s[t] += add;
        __syncthreads();
    }
    if (i < n) {
        g_rowptr[i] = s[t] - v;                  // exclusive within block
        g_dis[i]    = rsqrtf((float)(v + 1));    // +1 self loop
    }
    if (t == 1023) g_bsum[blockIdx.x] = s[1023];
}

// ---- launch 4: cross-block offset (inline spine) + cursor reset ----------
__global__ void scan3_k(int n, int nb) {
    __shared__ int sb[128];
    __shared__ int base;
    int t = threadIdx.x;
    if (t < nb) sb[t] = g_bsum[t];
    __syncthreads();
    if (t == 0) {
        int a = 0;
        for (int j = 0; j < blockIdx.x; j++) a += sb[j];
        base = a;
    }
    __syncthreads();
    int i = blockIdx.x * 1024 + t;
    if (i < n) {
        g_rowptr[i] += base;
        g_cursor[i] = 0;
    }
}

// ---- launch 5: CSR fill ---------------------------------------------------
__global__ void fill_k(const void* __restrict__ ei, int E) {
    int e = blockIdx.x * blockDim.x + threadIdx.x;
    if (e >= E) return;
    int s = (int)edge_at(ei, e);
    int d = (int)edge_at(ei, (long long)E + e);
    float nw = g_dis[s] * g_dis[d];
    int slot = g_rowptr[d] + atomicAdd(&g_cursor[d], 1);
    if (slot < MAXE) g_edges[slot] = make_int2(s, __float_as_int(nw));
}

// ---- copy x into hcat columns [0,128), row stride 512 --------------------
__global__ void copy_x_k(const float* __restrict__ x, float* __restrict__ hcat, int n) {
    long long idx = (long long)blockIdx.x * blockDim.x + threadIdx.x;
    if (idx >= (long long)n * 32) return;
    int i  = (int)(idx >> 5);
    int c4 = (int)(idx & 31);
    float4 v = ((const float4*)x)[(long long)i * 32 + c4];
    ((float4*)hcat)[(long long)i * 128 + c4] = v;
}

// ---- GEMM: h[n,128] = in[n(strided),128] @ W[128,128] --------------------
// 64 nodes/block, 256 threads, thread tile = 8 nodes x 4 channels.
// k chunked by 4: per chunk 8 LDS.128 (x, broadcast) + 4 LDS.128 (W)
// + 128 FFMA per thread -> FFMA:LDS = 10.7.
__global__ void gemm128_k(const float* __restrict__ in, int in_stride,
                          const float* __restrict__ W,
                          float* __restrict__ h, int n) {
    extern __shared__ float smem[];
    float* sW = smem;                 // [128][128] = 64 KB
    float* sX = smem + 128 * 128;     // [64][132]  = 33.8 KB

    int node0 = blockIdx.x * 64;

    for (int idx = threadIdx.x; idx < 4096; idx += 256)
        ((float4*)sW)[idx] = ((const float4*)W)[idx];
    for (int idx = threadIdx.x; idx < 2048; idx += 256) {
        int row = idx >> 5, c4 = idx & 31;
        float4 v = make_float4(0.f, 0.f, 0.f, 0.f);
        if (node0 + row < n)
            v = *(const float4*)(in + (long long)(node0 + row) * in_stride + c4 * 4);
        float* d = &sX[row * 132 + c4 * 4];
        d[0] = v.x; d[1] = v.y; d[2] = v.z; d[3] = v.w;
    }
    __syncthreads();

    int ch4  = threadIdx.x & 31;     // channels ch4*4 .. +3
    int ngrp = threadIdx.x >> 5;     // nodes ngrp*8 .. +7

    float4 acc[8];
#pragma unroll
    for (int i = 0; i < 8; i++) acc[i] = make_float4(0.f, 0.f, 0.f, 0.f);

    const float* xb = &sX[ngrp * 8 * 132];
    const float* wb = &sW[ch4 * 4];

    for (int k4 = 0; k4 < 32; k4++) {
        float4 xv[8];
#pragma unroll
        for (int i = 0; i < 8; i++)
            xv[i] = *(const float4*)&xb[i * 132 + k4 * 4];
#pragma unroll
        for (int kk = 0; kk < 4; kk++) {
            float4 wv = *(const float4*)&wb[(k4 * 4 + kk) * 128];
#pragma unroll
            for (int i = 0; i < 8; i++) {
                float x1 = (kk == 0) ? xv[i].x : (kk == 1) ? xv[i].y
                         : (kk == 2) ? xv[i].z : xv[i].w;
                acc[i].x += x1 * wv.x;
                acc[i].y += x1 * wv.y;
                acc[i].z += x1 * wv.z;
                acc[i].w += x1 * wv.w;
            }
        }
    }

#pragma unroll
    for (int i = 0; i < 8; i++) {
        int node = node0 + ngrp * 8 + i;
        if (node < n)
            *(float4*)(h + (long long)node * 128 + ch4 * 4) = acc[i];
    }
}

// ---- aggregation: warp per dst node, no atomics --------------------------
// chunk-of-8 unroll: mean deg=16 -> ~20 gather steps vs 32 with full padding
__global__ void agg_k(const float* __restrict__ h, const float* __restrict__ bias,
                      float* __restrict__ out, int n) {
    int warp = (int)(((long long)blockIdx.x * blockDim.x + threadIdx.x) >> 5);
    int lane = threadIdx.x & 31;
    if (warp >= n) return;

    int node = warp;
    int beg = g_rowptr[node];
    int cnt = g_deg[node];

    float di = g_dis[node];
    float d2 = di * di;

    float4 hv = __ldg(((const float4*)(h + (long long)node * 128)) + lane);
    float4 bv = __ldg(((const float4*)bias) + lane);
    float4 acc = make_float4(hv.x * d2 + bv.x, hv.y * d2 + bv.y,
                             hv.z * d2 + bv.z, hv.w * d2 + bv.w);

    for (int base = 0; base < cnt; base += 32) {
        int e = base + lane;
        int2 p = make_int2(0, 0);                 // src=0 (hot), w=0 pad
        if (e < cnt) p = __ldg(&g_edges[beg + e]);
        int src = p.x;
        float nw = __int_as_float(p.y);
        int m = min(32, cnt - base);
        for (int c = 0; c < m; c += 8) {
            // 8 independent batched gathers; lanes beyond m contribute w=0
#pragma unroll
            for (int j = 0; j < 8; j++) {
                int jj = c + j;
                int   s = __shfl_sync(0xffffffffu, src, jj);
                float w = __shfl_sync(0xffffffffu, nw,  jj);
                float4 v = __ldg(((const float4*)(h + (long long)s * 128)) + lane);
                acc.x += v.x * w; acc.y += v.y * w; acc.z += v.z * w; acc.w += v.w * w;
            }
        }
    }
    ((float4*)(out + (long long)node * 512))[lane] = acc;
}

// ---- final head: labels = hcat[n,512] @ W_lin[512,16] + b ----------------
__global__ void final_k(const float* __restrict__ hcat, const float* __restrict__ Wl,
                        const float* __restrict__ bl, float* __restrict__ out, int n) {
    __shared__ float sW[512 * 16];
    __shared__ float sB[16];
    for (int idx = threadIdx.x; idx < 512 * 16 / 4; idx += blockDim.x)
        ((float4*)sW)[idx] = ((const float4*)Wl)[idx];
    if (threadIdx.x < 16) sB[threadIdx.x] = bl[threadIdx.x];
    __syncthreads();

    int i = blockIdx.x * blockDim.x + threadIdx.x;
    if (i >= n) return;

    float4 acc[4];
#pragma unroll
    for (int j = 0; j < 4; j++)
        acc[j] = make_float4(sB[j * 4], sB[j * 4 + 1], sB[j * 4 + 2], sB[j * 4 + 3]);

    const float4* row = (const float4*)(hcat + (long long)i * 512);
#pragma unroll 4
    for (int k4 = 0; k4 < 128; k4++) {
        float4 r = row[k4];
        float rv[4] = {r.x, r.y, r.z, r.w};
#pragma unroll
        for (int kk = 0; kk < 4; kk++) {
            int k = k4 * 4 + kk;
            const float4* wr = (const float4*)&sW[k * 16];
#pragma unroll
            for (int j = 0; j < 4; j++) {
                float4 wv = wr[j];
                acc[j].x += rv[kk] * wv.x;
                acc[j].y += rv[kk] * wv.y;
                acc[j].z += rv[kk] * wv.z;
                acc[j].w += rv[kk] * wv.w;
            }
        }
    }
    float4* o = (float4*)(out + (long long)i * 16);
#pragma unroll
    for (int j = 0; j < 4; j++) o[j] = acc[j];
}

// --------------------------------------------------------------------------
extern "C" void kernel_launch(void* const* d_in, const int* in_sizes, int n_in,
                              void* d_out, int out_size) {
    const float* x   = (const float*)d_in[0];
    const void*  ei  = d_in[1];
    const float* W1  = (const float*)d_in[2];
    const float* b1  = (const float*)d_in[3];
    const float* W2  = (const float*)d_in[4];
    const float* b2  = (const float*)d_in[5];
    const float* W3  = (const float*)d_in[6];
    const float* b3  = (const float*)d_in[7];
    const float* Wl  = (const float*)d_in[8];
    const float* bl  = (const float*)d_in[9];

    int n = in_sizes[0] / IN_C;
    int E = in_sizes[1] / 2;

    float* out = (float*)d_out;

    float* hcat;
    if ((long long)out_size >= (long long)n * (NCLS + 512)) {
        hcat = out + (long long)n * NCLS;
    } else {
        cudaGetSymbolAddress((void**)&hcat, g_hcat);
    }

    float* d_h;
    cudaGetSymbolAddress((void**)&d_h, g_h);

    const int T = 256;
    int gemm_smem = 128 * 128 * 4 + 64 * 132 * 4;   // 99.3 KB
    cudaFuncSetAttribute(gemm128_k, cudaFuncAttributeMaxDynamicSharedMemorySize, gemm_smem);

    int nb1024 = (n + 1023) / 1024;
    long long v4 = (long long)n * 32;

    // launch order keeps gemm1 at profiled slot (index 3)
    init_k<<<(n + T - 1) / T, T>>>(ei, n);                              // 0
    deg_count_k<<<(E + T - 1) / T, T>>>(ei, E);                         // 1
    scan1_k<<<nb1024, 1024>>>(n);                                       // 2
    gemm128_k<<<(n + 63) / 64, T, gemm_smem>>>(x, 128, W1, d_h, n);     // 3 <- ncu
    scan3_k<<<nb1024, 1024>>>(n, nb1024);                               // 4
    fill_k<<<(E + T - 1) / T, T>>>(ei, E);                              // 5
    copy_x_k<<<(unsigned)((v4 + T - 1) / T), T>>>(x, hcat, n);          // 6

    const float* Ws[3] = {W1, W2, W3};
    const float* bs[3] = {b1, b2, b3};
    for (int l = 0; l < 3; l++) {
        float* out_ptr = hcat + (l + 1) * 128;
        if (l > 0) {
            gemm128_k<<<(n + 63) / 64, T, gemm_smem>>>(hcat + l * 128, 512, Ws[l], d_h, n);
        }
        int AT = 512;
        int agg_blocks = (n * 32 + AT - 1) / AT;
        agg_k<<<agg_blocks, AT>>>(d_h, bs[l], out_ptr, n);
    }

    final_k<<<(n + T - 1) / T, T>>>(hcat, Wl, bl, out, n);
}